// round 2
// baseline (speedup 1.0000x reference)
#include <cuda_runtime.h>
#include <cuda_bf16.h>
#include <cstddef>

// Problem constants
#define BB   512
#define AA   100
#define HH   1024
#define INN  77          // S*T = 7*11
#define GG   4096        // 4*H
#define M1   (AA*BB)     // 51200
#define BH   (BB*HH)     // 524288

// ---------------- scratch (device globals; no allocation allowed) ----------------
__device__ float g_xr [(size_t)M1 * INN];           // reordered inputs [A*B, 77]
__device__ float g_emb[(size_t)M1 * HH];            // embedded [A*B, H]
__device__ float g_gx [(size_t)M1 * GG];            // precomputed input gates [A*B, 4H]
__device__ float g_gh [(size_t)BB * GG];            // recurrent gates for current step
__device__ float g_h  [BH];
__device__ float g_c  [BH];
__device__ float g_bias[GG];

// ---------------- reorder: inputs[b, a*S+s, t] -> xr[(a*B+b)*IN + i] ----------------
__global__ void reorder_kernel(const float* __restrict__ inputs) {
    int idx = blockIdx.x * blockDim.x + threadIdx.x;
    if (idx >= M1 * INN) return;
    int i = idx % INN;
    int r = idx / INN;        // r = a*B + b
    int b = r % BB;
    int a = r / BB;
    g_xr[idx] = inputs[(size_t)b * (AA * INN) + (size_t)a * INN + i];
}

__global__ void bias_init_kernel(const float* __restrict__ b_ih, const float* __restrict__ b_hh) {
    int j = blockIdx.x * blockDim.x + threadIdx.x;
    if (j < GG) g_bias[j] = b_ih[j] + b_hh[j];
}

__global__ void state_init_kernel(const float* __restrict__ h0, const float* __restrict__ c0) {
    int i = blockIdx.x * blockDim.x + threadIdx.x;
    if (i < BH) { g_h[i] = h0[i]; g_c[i] = c0[i]; }
}

// ---------------- generic SGEMM: C[M,N] = A[M,K] * B[N,K]^T (+ bias[N]) ----------------
// A row-major [M,K], B row-major [N,K]. M % BM == 0, N % BN == 0 guaranteed by caller.
template<int BM, int BN, int BK, int TM, int TN>
__global__ __launch_bounds__((BM/TM)*(BN/TN))
void sgemm_nt(const float* __restrict__ A, const float* __restrict__ Bm,
              const float* __restrict__ bias, float* __restrict__ C,
              int M, int N, int K) {
    __shared__ float As[BK][BM];
    __shared__ float Bs[BK][BN];
    constexpr int NTHREADS = (BM/TM)*(BN/TN);
    const int tid = threadIdx.x;
    const int tx = tid % (BN/TN);
    const int ty = tid / (BN/TN);
    const float* Ab = A + (size_t)blockIdx.y * BM * K;
    const float* Bb = Bm + (size_t)blockIdx.x * BN * K;

    float acc[TM][TN];
    #pragma unroll
    for (int i = 0; i < TM; i++)
        #pragma unroll
        for (int j = 0; j < TN; j++) acc[i][j] = 0.f;

    for (int k0 = 0; k0 < K; k0 += BK) {
        #pragma unroll
        for (int i = tid; i < BM * BK; i += NTHREADS) {
            int m = i / BK, k = i % BK;
            As[k][m] = (k0 + k < K) ? Ab[(size_t)m * K + k0 + k] : 0.f;
        }
        #pragma unroll
        for (int i = tid; i < BN * BK; i += NTHREADS) {
            int n = i / BK, k = i % BK;
            Bs[k][n] = (k0 + k < K) ? Bb[(size_t)n * K + k0 + k] : 0.f;
        }
        __syncthreads();
        #pragma unroll
        for (int k = 0; k < BK; k++) {
            float a[TM], b[TN];
            #pragma unroll
            for (int i = 0; i < TM; i++) a[i] = As[k][ty * TM + i];
            #pragma unroll
            for (int j = 0; j < TN; j++) b[j] = Bs[k][tx * TN + j];
            #pragma unroll
            for (int i = 0; i < TM; i++)
                #pragma unroll
                for (int j = 0; j < TN; j++)
                    acc[i][j] = fmaf(a[i], b[j], acc[i][j]);
        }
        __syncthreads();
    }

    #pragma unroll
    for (int i = 0; i < TM; i++) {
        size_t m = (size_t)blockIdx.y * BM + ty * TM + i;
        #pragma unroll
        for (int j = 0; j < TN; j++) {
            int n = blockIdx.x * BN + tx * TN + j;
            float v = acc[i][j];
            if (bias) v += bias[n];
            C[m * N + n] = v;
        }
    }
}

// ---------------- LSTM cell elementwise ----------------
__global__ void lstm_cell_kernel(const float* __restrict__ gx,   // [B, 4H] slice for step t
                                 const float* __restrict__ gh,   // [B, 4H]
                                 float* __restrict__ h,
                                 float* __restrict__ c,
                                 float* __restrict__ out_t) {    // d_out + t*B*H
    int idx = blockIdx.x * blockDim.x + threadIdx.x;
    if (idx >= BH) return;
    int b = idx / HH, hh = idx % HH;
    size_t base = (size_t)b * GG;
    float gi = gx[base + hh]          + gh[base + hh];
    float gf = gx[base + HH + hh]     + gh[base + HH + hh];
    float gg = gx[base + 2 * HH + hh] + gh[base + 2 * HH + hh];
    float go = gx[base + 3 * HH + hh] + gh[base + 3 * HH + hh];
    float i = 1.f / (1.f + expf(-gi));
    float f = 1.f / (1.f + expf(-gf));
    float g = tanhf(gg);
    float o = 1.f / (1.f + expf(-go));
    float cn = f * c[idx] + i * g;
    float hn = o * tanhf(cn);
    c[idx] = cn;
    h[idx] = hn;
    out_t[idx] = hn;
}

__global__ void copy_hc_kernel(float* __restrict__ dst) {  // dst = d_out + A*B*H
    int i = blockIdx.x * blockDim.x + threadIdx.x;
    if (i < BH) { dst[i] = g_h[i]; dst[BH + i] = g_c[i]; }
}

// ---------------- launch ----------------
extern "C" void kernel_launch(void* const* d_in, const int* in_sizes, int n_in,
                              void* d_out, int out_size) {
    const float* inputs = (const float*)d_in[0];
    const float* h0     = (const float*)d_in[1];
    const float* c0     = (const float*)d_in[2];
    const float* W_emb  = (const float*)d_in[3];
    const float* b_emb  = (const float*)d_in[4];
    const float* W_ih   = (const float*)d_in[5];
    const float* W_hh   = (const float*)d_in[6];
    const float* b_ih   = (const float*)d_in[7];
    const float* b_hh   = (const float*)d_in[8];
    float* out = (float*)d_out;

    // Resolve REAL device addresses of the scratch globals. (Passing the
    // __device__ symbols directly from host code passes the host shadow
    // address — that was the round-1 bug.) Pure host queries: graph-legal.
    float *p_xr, *p_emb, *p_gx, *p_gh, *p_h, *p_c, *p_bias;
    cudaGetSymbolAddress((void**)&p_xr,  g_xr);
    cudaGetSymbolAddress((void**)&p_emb, g_emb);
    cudaGetSymbolAddress((void**)&p_gx,  g_gx);
    cudaGetSymbolAddress((void**)&p_gh,  g_gh);
    cudaGetSymbolAddress((void**)&p_h,   g_h);
    cudaGetSymbolAddress((void**)&p_c,   g_c);
    cudaGetSymbolAddress((void**)&p_bias,g_bias);

    // prep
    reorder_kernel<<<(M1 * INN + 255) / 256, 256>>>(inputs);
    bias_init_kernel<<<(GG + 255) / 256, 256>>>(b_ih, b_hh);
    state_init_kernel<<<(BH + 255) / 256, 256>>>(h0, c0);

    // embed: emb[A*B, H] = xr[A*B, 77] @ W_emb[H,77]^T + b_emb
    sgemm_nt<128, 128, 8, 8, 8><<<dim3(HH / 128, M1 / 128), 256>>>(
        p_xr, W_emb, b_emb, p_emb, M1, HH, INN);

    // input gates for all steps: gx[A*B, 4H] = emb @ W_ih[4H,H]^T + (b_ih+b_hh)
    sgemm_nt<128, 128, 8, 8, 8><<<dim3(GG / 128, M1 / 128), 256>>>(
        p_emb, W_ih, p_bias, p_gx, M1, GG, HH);

    // recurrence
    for (int t = 0; t < AA; t++) {
        // gh[B, 4H] = h[B,H] @ W_hh[4H,H]^T
        sgemm_nt<64, 128, 8, 4, 8><<<dim3(GG / 128, BB / 64), 256>>>(
            p_h, W_hh, (const float*)nullptr, p_gh, BB, GG, HH);
        lstm_cell_kernel<<<(BH + 255) / 256, 256>>>(
            p_gx + (size_t)t * BB * GG, p_gh, p_h, p_c, out + (size_t)t * BH);
    }

    // final (h, c) after output — only if the harness buffer includes them
    if (out_size >= (AA + 2) * BH) {
        copy_hc_kernel<<<(BH + 255) / 256, 256>>>(out + (size_t)AA * BH);
    }
}

// round 4
// speedup vs baseline: 3.7910x; 3.7910x over previous
#include <cuda_runtime.h>
#include <cuda_bf16.h>
#include <cstdint>
#include <cstddef>

// Problem constants
#define BB   512
#define AA   100
#define HH   1024
#define INN  77          // S*T = 7*11
#define GG   4096        // 4*H
#define M1   (AA*BB)     // 51200
#define BH   (BB*HH)     // 524288

typedef __nv_bfloat16 bf16;

// ---------------- scratch (device globals; no allocation allowed) ----------------
__device__ float g_xr    [(size_t)M1 * INN];   // reordered inputs [A*B, 77]
__device__ bf16  g_ehi   [(size_t)M1 * HH];    // embedded hi (bf16)
__device__ bf16  g_elo   [(size_t)M1 * HH];    // embedded lo (bf16)
__device__ float g_gx    [(size_t)M1 * GG];    // precomputed input gates [A*B, 4H]
__device__ float g_gh    [(size_t)BB * GG];    // recurrent gates, current step
__device__ bf16  g_hhi   [BH];
__device__ bf16  g_hlo   [BH];
__device__ float g_c     [BH];
__device__ float g_bias  [GG];
__device__ bf16  g_wih_hi[(size_t)GG * HH];
__device__ bf16  g_wih_lo[(size_t)GG * HH];
__device__ bf16  g_whh_hi[(size_t)GG * HH];
__device__ bf16  g_whh_lo[(size_t)GG * HH];

// ================= PTX helpers (sm_80+ standard; NO arch-'a' features) =========
__device__ __forceinline__ uint32_t smem_u32(const void* p) {
    uint32_t a;
    asm("{ .reg .u64 t; cvta.to.shared.u64 t, %1; cvt.u32.u64 %0, t; }" : "=r"(a) : "l"(p));
    return a;
}
#define SMEM_SWIZZLE_128B(o) ((o) ^ (((o) >> 3) & 0x70))

__device__ __forceinline__ void cp_async16(uint32_t smem_addr, const void* gptr) {
    asm volatile("cp.async.cg.shared.global [%0], [%1], 16;"
                 :: "r"(smem_addr), "l"(gptr) : "memory");
}
#define CP_COMMIT() asm volatile("cp.async.commit_group;" ::: "memory")
#define CP_WAIT(n)  asm volatile("cp.async.wait_group %0;" :: "n"(n) : "memory")

__device__ __forceinline__ void ldsm_x4(uint32_t addr, uint32_t& r0, uint32_t& r1,
                                        uint32_t& r2, uint32_t& r3) {
    asm volatile("ldmatrix.sync.aligned.m8n8.x4.shared.b16 {%0,%1,%2,%3}, [%4];"
                 : "=r"(r0), "=r"(r1), "=r"(r2), "=r"(r3) : "r"(addr));
}

__device__ __forceinline__ void mma_bf16(float* d, const uint32_t* a, const uint32_t* b) {
    asm volatile(
        "mma.sync.aligned.m16n8k16.row.col.f32.bf16.bf16.f32 "
        "{%0,%1,%2,%3}, {%4,%5,%6,%7}, {%8,%9}, {%0,%1,%2,%3};"
        : "+f"(d[0]), "+f"(d[1]), "+f"(d[2]), "+f"(d[3])
        : "r"(a[0]), "r"(a[1]), "r"(a[2]), "r"(a[3]), "r"(b[0]), "r"(b[1]));
}

// ================= prep kernels =================
__global__ void reorder_kernel(const float* __restrict__ inputs) {
    int idx = blockIdx.x * blockDim.x + threadIdx.x;
    if (idx >= M1 * INN) return;
    int i = idx % INN;
    int r = idx / INN;        // r = a*B + b
    int b = r % BB;
    int a = r / BB;
    g_xr[idx] = inputs[(size_t)b * (AA * INN) + (size_t)a * INN + i];
}

__global__ void bias_init_kernel(const float* __restrict__ b_ih, const float* __restrict__ b_hh) {
    int j = blockIdx.x * blockDim.x + threadIdx.x;
    if (j < GG) g_bias[j] = b_ih[j] + b_hh[j];
}

__global__ void state_init_kernel(const float* __restrict__ h0, const float* __restrict__ c0) {
    int i = blockIdx.x * blockDim.x + threadIdx.x;
    if (i >= BH) return;
    float h = h0[i];
    bf16 hb = __float2bfloat16(h);
    g_hhi[i] = hb;
    g_hlo[i] = __float2bfloat16(h - __bfloat162float(hb));
    g_c[i] = c0[i];
}

__global__ void decomp_bf16_kernel(const float* __restrict__ src, bf16* __restrict__ hi,
                                   bf16* __restrict__ lo, int n) {
    int i = blockIdx.x * blockDim.x + threadIdx.x;
    if (i >= n) return;
    float v = src[i];
    bf16 hb = __float2bfloat16(v);
    hi[i] = hb;
    lo[i] = __float2bfloat16(v - __bfloat162float(hb));
}

// ============ SIMT SGEMM for embedding (K=77) -> bf16 hi/lo ============
template<int BM, int BN, int BK, int TM, int TN>
__global__ __launch_bounds__((BM/TM)*(BN/TN))
void sgemm_nt_hilo(const float* __restrict__ A, const float* __restrict__ Bm,
                   const float* __restrict__ bias, bf16* __restrict__ Chi,
                   bf16* __restrict__ Clo, int M, int N, int K) {
    __shared__ float As[BK][BM];
    __shared__ float Bs[BK][BN];
    constexpr int NTHREADS = (BM/TM)*(BN/TN);
    const int tid = threadIdx.x;
    const int tx = tid % (BN/TN);
    const int ty = tid / (BN/TN);
    const float* Ab = A + (size_t)blockIdx.y * BM * K;
    const float* Bb = Bm + (size_t)blockIdx.x * BN * K;

    float acc[TM][TN];
    #pragma unroll
    for (int i = 0; i < TM; i++)
        #pragma unroll
        for (int j = 0; j < TN; j++) acc[i][j] = 0.f;

    for (int k0 = 0; k0 < K; k0 += BK) {
        #pragma unroll
        for (int i = tid; i < BM * BK; i += NTHREADS) {
            int m = i / BK, k = i % BK;
            As[k][m] = (k0 + k < K) ? Ab[(size_t)m * K + k0 + k] : 0.f;
        }
        #pragma unroll
        for (int i = tid; i < BN * BK; i += NTHREADS) {
            int n = i / BK, k = i % BK;
            Bs[k][n] = (k0 + k < K) ? Bb[(size_t)n * K + k0 + k] : 0.f;
        }
        __syncthreads();
        #pragma unroll
        for (int k = 0; k < BK; k++) {
            float a[TM], b[TN];
            #pragma unroll
            for (int i = 0; i < TM; i++) a[i] = As[k][ty * TM + i];
            #pragma unroll
            for (int j = 0; j < TN; j++) b[j] = Bs[k][tx * TN + j];
            #pragma unroll
            for (int i = 0; i < TM; i++)
                #pragma unroll
                for (int j = 0; j < TN; j++)
                    acc[i][j] = fmaf(a[i], b[j], acc[i][j]);
        }
        __syncthreads();
    }

    #pragma unroll
    for (int i = 0; i < TM; i++) {
        size_t m = (size_t)blockIdx.y * BM + ty * TM + i;
        #pragma unroll
        for (int j = 0; j < TN; j++) {
            int n = blockIdx.x * BN + tx * TN + j;
            float v = acc[i][j] + bias[n];
            bf16 hb = __float2bfloat16(v);
            Chi[m * N + n] = hb;
            Clo[m * N + n] = __float2bfloat16(v - __bfloat162float(hb));
        }
    }
}

// ================= bf16-split tensor-core GEMM (mma.sync) =================
// C[M,N] = A*B^T where A = Ahi+Alo, B = Bhi+Blo (bf16 pairs), fp32 accum.
// 3 passes over K: (Ahi,Bhi), (Ahi,Blo), (Alo,Bhi). AlBl dropped (~2^-18).
// CTA tile 128x128, 8 warps (2x4), warp tile 64x32, K-chunk 64, cp.async 2-stage.
#define CHUNK 64
#define OP_TILE_BYTES 16384            // 128 rows * 128 bytes
#define STAGE_BYTES (2 * OP_TILE_BYTES)
#define SMEM_GEMM_BYTES (2 * STAGE_BYTES + 1024)

__global__ __launch_bounds__(256, 2)
void mma_gemm_3p(const bf16* __restrict__ Ahi, const bf16* __restrict__ Alo,
                 const bf16* __restrict__ Bhi, const bf16* __restrict__ Blo,
                 const float* __restrict__ bias, float* __restrict__ C,
                 int K, int ldc) {
    extern __shared__ char sm[];
    const uint32_t base = (smem_u32(sm) + 1023u) & ~1023u;
    const int tid = threadIdx.x;
    const int wid = tid >> 5, lane = tid & 31;
    const int wm = (wid >> 2) * 64;    // warp m offset within tile
    const int wn = (wid & 3) * 32;     // warp n offset within tile

    const int cpp = K / CHUNK;         // chunks per pass
    const int total = 3 * cpp;

    const bf16* Aps[3] = {Ahi, Ahi, Alo};
    const bf16* Bps[3] = {Bhi, Blo, Bhi};

    float acc[4][4][4];
    #pragma unroll
    for (int mi = 0; mi < 4; mi++)
        #pragma unroll
        for (int nj = 0; nj < 4; nj++)
            #pragma unroll
            for (int q = 0; q < 4; q++) acc[mi][nj][q] = 0.f;

    auto prefetch = [&](int ch) {
        const int p = ch / cpp;
        const int kc = (ch % cpp) * CHUNK;
        const bf16* Ab = Aps[p] + (size_t)blockIdx.y * 128 * K + kc;
        const bf16* Bb = Bps[p] + (size_t)blockIdx.x * 128 * K + kc;
        const uint32_t sA = base + (uint32_t)(ch & 1) * STAGE_BYTES;
        const uint32_t sB = sA + OP_TILE_BYTES;
        #pragma unroll
        for (int it = 0; it < 4; it++) {
            const int idx = it * 256 + tid;       // 0..1023
            const int row = idx >> 3;
            const int c8  = idx & 7;              // 16B group within 128B row
            const uint32_t off = SMEM_SWIZZLE_128B((uint32_t)(row * 128 + c8 * 16));
            cp_async16(sA + off, Ab + (size_t)row * K + c8 * 8);
            cp_async16(sB + off, Bb + (size_t)row * K + c8 * 8);
        }
    };

    prefetch(0);
    CP_COMMIT();

    const int tsel = lane >> 3, rin = lane & 7;

    for (int ch = 0; ch < total; ch++) {
        if (ch + 1 < total) {
            prefetch(ch + 1);
            CP_COMMIT();
            CP_WAIT(1);
        } else {
            CP_WAIT(0);
        }
        __syncthreads();

        const uint32_t sA = base + (uint32_t)(ch & 1) * STAGE_BYTES;
        const uint32_t sB = sA + OP_TILE_BYTES;

        #pragma unroll
        for (int kk = 0; kk < CHUNK; kk += 16) {
            const int col = kk + (tsel >> 1) * 8;
            uint32_t a[4][4];
            #pragma unroll
            for (int mi = 0; mi < 4; mi++) {
                const int row = wm + mi * 16 + (tsel & 1) * 8 + rin;
                const uint32_t addr = sA + SMEM_SWIZZLE_128B((uint32_t)(row * 128 + col * 2));
                ldsm_x4(addr, a[mi][0], a[mi][1], a[mi][2], a[mi][3]);
            }
            uint32_t b[4][2];
            #pragma unroll
            for (int g = 0; g < 2; g++) {
                const int row = wn + g * 16 + (tsel & 1) * 8 + rin;
                const uint32_t addr = sB + SMEM_SWIZZLE_128B((uint32_t)(row * 128 + col * 2));
                uint32_t r0, r1, r2, r3;
                ldsm_x4(addr, r0, r1, r2, r3);
                b[g * 2 + 0][0] = r0; b[g * 2 + 0][1] = r2;
                b[g * 2 + 1][0] = r1; b[g * 2 + 1][1] = r3;
            }
            #pragma unroll
            for (int mi = 0; mi < 4; mi++)
                #pragma unroll
                for (int nj = 0; nj < 4; nj++)
                    mma_bf16(acc[mi][nj], a[mi], b[nj]);
        }
        __syncthreads();
    }

    // epilogue
    const int r0 = lane >> 2;
    const int c0 = (lane & 3) * 2;
    #pragma unroll
    for (int mi = 0; mi < 4; mi++) {
        const size_t m0 = (size_t)blockIdx.y * 128 + wm + mi * 16;
        #pragma unroll
        for (int nj = 0; nj < 4; nj++) {
            const int n = blockIdx.x * 128 + wn + nj * 8 + c0;
            float bx = 0.f, by = 0.f;
            if (bias) { bx = bias[n]; by = bias[n + 1]; }
            float2 v0 = make_float2(acc[mi][nj][0] + bx, acc[mi][nj][1] + by);
            float2 v1 = make_float2(acc[mi][nj][2] + bx, acc[mi][nj][3] + by);
            *(float2*)(C + (m0 + r0) * (size_t)ldc + n) = v0;
            *(float2*)(C + (m0 + r0 + 8) * (size_t)ldc + n) = v1;
        }
    }
}

// ---------------- LSTM cell elementwise ----------------
__global__ void lstm_cell_kernel(const float* __restrict__ gx, float* __restrict__ out_t) {
    int idx = blockIdx.x * blockDim.x + threadIdx.x;
    if (idx >= BH) return;
    int b = idx / HH, hh = idx % HH;
    size_t base = (size_t)b * GG;
    float gi = gx[base + hh]          + g_gh[base + hh];
    float gf = gx[base + HH + hh]     + g_gh[base + HH + hh];
    float gg = gx[base + 2 * HH + hh] + g_gh[base + 2 * HH + hh];
    float go = gx[base + 3 * HH + hh] + g_gh[base + 3 * HH + hh];
    float i = 1.f / (1.f + expf(-gi));
    float f = 1.f / (1.f + expf(-gf));
    float g = tanhf(gg);
    float o = 1.f / (1.f + expf(-go));
    float cn = f * g_c[idx] + i * g;
    float hn = o * tanhf(cn);
    g_c[idx] = cn;
    bf16 hb = __float2bfloat16(hn);
    g_hhi[idx] = hb;
    g_hlo[idx] = __float2bfloat16(hn - __bfloat162float(hb));
    out_t[idx] = hn;
}

__global__ void copy_hc_kernel(const float* __restrict__ last_h, float* __restrict__ dst) {
    int i = blockIdx.x * blockDim.x + threadIdx.x;
    if (i < BH) { dst[i] = last_h[i]; dst[BH + i] = g_c[i]; }
}

// ---------------- launch ----------------
extern "C" void kernel_launch(void* const* d_in, const int* in_sizes, int n_in,
                              void* d_out, int out_size) {
    const float* inputs = (const float*)d_in[0];
    const float* h0     = (const float*)d_in[1];
    const float* c0     = (const float*)d_in[2];
    const float* W_emb  = (const float*)d_in[3];
    const float* b_emb  = (const float*)d_in[4];
    const float* W_ih   = (const float*)d_in[5];
    const float* W_hh   = (const float*)d_in[6];
    const float* b_ih   = (const float*)d_in[7];
    const float* b_hh   = (const float*)d_in[8];
    float* out = (float*)d_out;

    // Real device addresses of scratch globals (host-shadow trap otherwise).
    float *p_xr, *p_gx, *p_gh, *p_bias;
    bf16 *p_ehi, *p_elo, *p_hhi, *p_hlo;
    bf16 *p_wihh, *p_wihl, *p_whhh, *p_whhl;
    cudaGetSymbolAddress((void**)&p_xr,   g_xr);
    cudaGetSymbolAddress((void**)&p_ehi,  g_ehi);
    cudaGetSymbolAddress((void**)&p_elo,  g_elo);
    cudaGetSymbolAddress((void**)&p_gx,   g_gx);
    cudaGetSymbolAddress((void**)&p_gh,   g_gh);
    cudaGetSymbolAddress((void**)&p_hhi,  g_hhi);
    cudaGetSymbolAddress((void**)&p_hlo,  g_hlo);
    cudaGetSymbolAddress((void**)&p_bias, g_bias);
    cudaGetSymbolAddress((void**)&p_wihh, g_wih_hi);
    cudaGetSymbolAddress((void**)&p_wihl, g_wih_lo);
    cudaGetSymbolAddress((void**)&p_whhh, g_whh_hi);
    cudaGetSymbolAddress((void**)&p_whhl, g_whh_lo);

    cudaFuncSetAttribute(mma_gemm_3p, cudaFuncAttributeMaxDynamicSharedMemorySize,
                         SMEM_GEMM_BYTES);

    // prep
    reorder_kernel<<<(M1 * INN + 255) / 256, 256>>>(inputs);
    bias_init_kernel<<<(GG + 255) / 256, 256>>>(b_ih, b_hh);
    state_init_kernel<<<(BH + 255) / 256, 256>>>(h0, c0);
    decomp_bf16_kernel<<<(GG * HH + 255) / 256, 256>>>(W_ih, p_wihh, p_wihl, GG * HH);
    decomp_bf16_kernel<<<(GG * HH + 255) / 256, 256>>>(W_hh, p_whhh, p_whhl, GG * HH);

    // embed (SIMT fp32, K=77): emb = xr @ W_emb^T + b_emb -> bf16 hi/lo
    sgemm_nt_hilo<128, 128, 8, 8, 8><<<dim3(HH / 128, M1 / 128), 256>>>(
        p_xr, W_emb, b_emb, p_ehi, p_elo, M1, HH, INN);

    // gx = emb @ W_ih^T + bias  (tensor-core bf16 split)
    mma_gemm_3p<<<dim3(GG / 128, M1 / 128), 256, SMEM_GEMM_BYTES>>>(
        p_ehi, p_elo, p_wihh, p_wihl, p_bias, p_gx, HH, GG);

    // recurrence
    for (int t = 0; t < AA; t++) {
        mma_gemm_3p<<<dim3(GG / 128, BB / 128), 256, SMEM_GEMM_BYTES>>>(
            p_hhi, p_hlo, p_whhh, p_whhl, (const float*)nullptr, p_gh, HH, GG);
        lstm_cell_kernel<<<(BH + 255) / 256, 256>>>(
            p_gx + (size_t)t * BB * GG, out + (size_t)t * BH);
    }

    // final (h, c) after output — only if the harness buffer includes them
    if (out_size >= (AA + 2) * BH) {
        copy_hc_kernel<<<(BH + 255) / 256, 256>>>(out + (size_t)(AA - 1) * BH,
                                                  out + (size_t)AA * BH);
    }
}